// round 6
// baseline (speedup 1.0000x reference)
#include <cuda_runtime.h>
#include <cstdint>
#include <cstddef>

// ---------------------------------------------------------------------------
// Problem constants
// ---------------------------------------------------------------------------
#define E_DIM   1024
#define H_HEADS 16
#define D_HEAD  64
#define NTOK    8192          // B*S = 16*512
#define NROWS   49152         // 6 * NTOK
#define HID     1024

// ---------------------------------------------------------------------------
// Scratch: one big __device__ array (no cudaMalloc allowed).
// Layout (floats):
//   Q : [0,               50331648)   (reused as O-proj output later)
//   K : [50331648,       100663296)
//   V : [100663296,      150994944)
//   C : [150994944,      201326592)   (attention context)
//   F : [201326592,      209715200)   (fused, 8192x1024)
//   H : [209715200,      218103808)   (pre-LN2 hidden, 8192x1024)
// ---------------------------------------------------------------------------
#define OFF_Q 0ull
#define OFF_K 50331648ull
#define OFF_V 100663296ull
#define OFF_C 150994944ull
#define OFF_O OFF_Q
#define OFF_F 201326592ull
#define OFF_H 209715200ull

__device__ float g_scratch[218103808];

// ---------------------------------------------------------------------------
// SGEMM (NT): C[m,n] = sum_k A[m,k] * W[n,k] + bias[n]   (optional LeakyReLU)
// A: MxK row-major, W: NxK row-major. All dims multiples of tile sizes.
// BM=128, BN=128, BK=16, 256 threads, 8x8 register tile per thread.
// ---------------------------------------------------------------------------
#define BM 128
#define BN 128
#define BK 16

__global__ __launch_bounds__(256)
void sgemm_nt(const float* __restrict__ A, const float* __restrict__ W,
              const float* __restrict__ bias, float* __restrict__ C,
              int M, int N, int K, int act)
{
    __shared__ __align__(16) float As[BK][BM + 4];
    __shared__ __align__(16) float Bs[BK][BN + 4];

    const int tid = threadIdx.x;
    const int m0  = blockIdx.y * BM;
    const int n0  = blockIdx.x * BN;
    const int tx  = tid & 15;         // 0..15
    const int ty  = tid >> 4;         // 0..15

    float acc[8][8];
#pragma unroll
    for (int i = 0; i < 8; i++)
#pragma unroll
        for (int j = 0; j < 8; j++) acc[i][j] = 0.f;

    for (int k0 = 0; k0 < K; k0 += BK) {
        // Load 128x16 tiles of A and W (512 float4 each; 2 per thread),
        // storing transposed so compute reads are vectorized.
#pragma unroll
        for (int i = 0; i < 2; i++) {
            int lin = tid + i * 256;          // 0..511
            int row = lin >> 2;               // 0..127
            int kc  = (lin & 3) << 2;         // 0,4,8,12
            float4 a = *(const float4*)(A + (size_t)(m0 + row) * K + k0 + kc);
            As[kc + 0][row] = a.x;
            As[kc + 1][row] = a.y;
            As[kc + 2][row] = a.z;
            As[kc + 3][row] = a.w;
            float4 b = *(const float4*)(W + (size_t)(n0 + row) * K + k0 + kc);
            Bs[kc + 0][row] = b.x;
            Bs[kc + 1][row] = b.y;
            Bs[kc + 2][row] = b.z;
            Bs[kc + 3][row] = b.w;
        }
        __syncthreads();

#pragma unroll
        for (int kk = 0; kk < BK; kk++) {
            float a[8], b[8];
            *(float4*)&a[0] = *(const float4*)&As[kk][ty * 8];
            *(float4*)&a[4] = *(const float4*)&As[kk][ty * 8 + 4];
            *(float4*)&b[0] = *(const float4*)&Bs[kk][tx * 8];
            *(float4*)&b[4] = *(const float4*)&Bs[kk][tx * 8 + 4];
#pragma unroll
            for (int i = 0; i < 8; i++)
#pragma unroll
                for (int j = 0; j < 8; j++)
                    acc[i][j] += a[i] * b[j];
        }
        __syncthreads();
    }

    // Epilogue: bias (+ optional LeakyReLU), vectorized stores.
#pragma unroll
    for (int i = 0; i < 8; i++) {
        size_t crow = (size_t)(m0 + ty * 8 + i) * N + n0 + tx * 8;
#pragma unroll
        for (int jj = 0; jj < 8; jj += 4) {
            float4 bsv = *(const float4*)(bias + n0 + tx * 8 + jj);
            float4 o;
            o.x = acc[i][jj + 0] + bsv.x;
            o.y = acc[i][jj + 1] + bsv.y;
            o.z = acc[i][jj + 2] + bsv.z;
            o.w = acc[i][jj + 3] + bsv.w;
            if (act) {
                o.x = o.x >= 0.f ? o.x : 0.01f * o.x;
                o.y = o.y >= 0.f ? o.y : 0.01f * o.y;
                o.z = o.z >= 0.f ? o.z : 0.01f * o.z;
                o.w = o.w >= 0.f ? o.w : 0.01f * o.w;
            }
            *(float4*)(C + crow + jj) = o;
        }
    }
}

// ---------------------------------------------------------------------------
// Tiny 6x6 attention: one warp per (token n, head h).
// Q/K/V layout: row r = j*NTOK + n, cols = h*64 + d.
// ---------------------------------------------------------------------------
__device__ __forceinline__ float warpAllSum(float v)
{
#pragma unroll
    for (int o = 16; o; o >>= 1) v += __shfl_xor_sync(0xffffffffu, v, o);
    return v;
}

__global__ __launch_bounds__(256)
void attn6_kernel(const float* __restrict__ Q, const float* __restrict__ K,
                  const float* __restrict__ V, float* __restrict__ C)
{
    const int warp = threadIdx.x >> 5;
    const int lane = threadIdx.x & 31;
    const int idx  = blockIdx.x * 8 + warp;    // 0 .. NTOK*H_HEADS-1
    const int n = idx >> 4;
    const int h = idx & 15;

    const size_t base = (size_t)n * E_DIM + h * D_HEAD + 2 * lane;

    float2 q[6], k[6], v[6];
#pragma unroll
    for (int j = 0; j < 6; j++) {
        size_t off = base + (size_t)j * NTOK * E_DIM;
        q[j] = *(const float2*)(Q + off);
        k[j] = *(const float2*)(K + off);
        v[j] = *(const float2*)(V + off);
    }

    float s[6][6];
#pragma unroll
    for (int i = 0; i < 6; i++)
#pragma unroll
        for (int j = 0; j < 6; j++) {
            float p = q[i].x * k[j].x + q[i].y * k[j].y;
            s[i][j] = warpAllSum(p) * 0.125f;      // 1/sqrt(64)
        }

#pragma unroll
    for (int i = 0; i < 6; i++) {
        float mx = s[i][0];
#pragma unroll
        for (int j = 1; j < 6; j++) mx = fmaxf(mx, s[i][j]);
        float se = 0.f;
#pragma unroll
        for (int j = 0; j < 6; j++) { s[i][j] = __expf(s[i][j] - mx); se += s[i][j]; }
        float inv = 1.f / se;
#pragma unroll
        for (int j = 0; j < 6; j++) s[i][j] *= inv;
    }

#pragma unroll
    for (int i = 0; i < 6; i++) {
        float2 acc = make_float2(0.f, 0.f);
#pragma unroll
        for (int j = 0; j < 6; j++) {
            acc.x += s[i][j] * v[j].x;
            acc.y += s[i][j] * v[j].y;
        }
        *(float2*)(C + base + (size_t)i * NTOK * E_DIM) = acc;
    }
}

// ---------------------------------------------------------------------------
// Block-wide allreduce of (sum, sumsq)
// ---------------------------------------------------------------------------
__device__ __forceinline__ float2 blockAllReduce2(float2 v)
{
    __shared__ float2 sh[8];
    const int lane = threadIdx.x & 31;
    const int wid  = threadIdx.x >> 5;
#pragma unroll
    for (int o = 16; o; o >>= 1) {
        v.x += __shfl_xor_sync(0xffffffffu, v.x, o);
        v.y += __shfl_xor_sync(0xffffffffu, v.y, o);
    }
    if (lane == 0) sh[wid] = v;
    __syncthreads();
    if (wid == 0) {
        float2 t = (lane < 8) ? sh[lane] : make_float2(0.f, 0.f);
#pragma unroll
        for (int o = 4; o; o >>= 1) {
            t.x += __shfl_xor_sync(0xffffffffu, t.x, o);
            t.y += __shfl_xor_sync(0xffffffffu, t.y, o);
        }
        if (lane == 0) sh[0] = t;
    }
    __syncthreads();
    float2 r = sh[0];
    __syncthreads();
    return r;
}

// ---------------------------------------------------------------------------
// LN1(out + st) per (j, n) row, then weighted fusion over j -> F[n, 1024]
// One block per token n; 256 threads x float4.
// ---------------------------------------------------------------------------
__global__ __launch_bounds__(256)
void ln1_fuse_kernel(const float* __restrict__ OP, const float* __restrict__ ST,
                     const float* __restrict__ g, const float* __restrict__ b,
                     const float* __restrict__ fw, float* __restrict__ F)
{
    const int n   = blockIdx.x;
    const int tid = threadIdx.x;

    // softmax of fusion weights (6 values, each thread redundantly)
    float w[6];
    {
        float f[6], mx = -1e30f;
#pragma unroll
        for (int j = 0; j < 6; j++) { f[j] = fw[j]; mx = fmaxf(mx, f[j]); }
        float se = 0.f;
#pragma unroll
        for (int j = 0; j < 6; j++) { w[j] = expf(f[j] - mx); se += w[j]; }
        float inv = 1.f / se;
#pragma unroll
        for (int j = 0; j < 6; j++) w[j] *= inv;
    }

    float4 gg = ((const float4*)g)[tid];
    float4 bb = ((const float4*)b)[tid];
    float4 acc = make_float4(0.f, 0.f, 0.f, 0.f);

    for (int j = 0; j < 6; j++) {
        size_t roff = ((size_t)j * NTOK + n) * E_DIM;
        float4 x = ((const float4*)(OP + roff))[tid];
        float4 y = ((const float4*)(ST + roff))[tid];
        x.x += y.x; x.y += y.y; x.z += y.z; x.w += y.w;

        float2 r = make_float2(x.x + x.y + x.z + x.w,
                               x.x * x.x + x.y * x.y + x.z * x.z + x.w * x.w);
        r = blockAllReduce2(r);
        float mean = r.x * (1.f / 1024.f);
        float var  = r.y * (1.f / 1024.f) - mean * mean;
        float rstd = rsqrtf(var + 1e-5f);

        acc.x += w[j] * ((x.x - mean) * rstd * gg.x + bb.x);
        acc.y += w[j] * ((x.y - mean) * rstd * gg.y + bb.y);
        acc.z += w[j] * ((x.z - mean) * rstd * gg.z + bb.z);
        acc.w += w[j] * ((x.w - mean) * rstd * gg.w + bb.w);
    }
    ((float4*)F)[(size_t)n * 256 + tid] = acc;
}

// ---------------------------------------------------------------------------
// LN2 per token row (hidden already has bias + LeakyReLU applied)
// ---------------------------------------------------------------------------
__global__ __launch_bounds__(256)
void ln2_kernel(const float* __restrict__ Hbuf, const float* __restrict__ g,
                const float* __restrict__ b, float* __restrict__ out)
{
    const int n   = blockIdx.x;
    const int tid = threadIdx.x;

    float4 x = ((const float4*)(Hbuf + (size_t)n * HID))[tid];
    float2 r = make_float2(x.x + x.y + x.z + x.w,
                           x.x * x.x + x.y * x.y + x.z * x.z + x.w * x.w);
    r = blockAllReduce2(r);
    float mean = r.x * (1.f / 1024.f);
    float var  = r.y * (1.f / 1024.f) - mean * mean;
    float rstd = rsqrtf(var + 1e-5f);

    float4 gg = ((const float4*)g)[tid];
    float4 bb = ((const float4*)b)[tid];
    float4 o;
    o.x = (x.x - mean) * rstd * gg.x + bb.x;
    o.y = (x.y - mean) * rstd * gg.y + bb.y;
    o.z = (x.z - mean) * rstd * gg.z + bb.z;
    o.w = (x.w - mean) * rstd * gg.w + bb.w;
    ((float4*)(out + (size_t)n * HID))[tid] = o;
}

// ---------------------------------------------------------------------------
// Launch
// ---------------------------------------------------------------------------
extern "C" void kernel_launch(void* const* d_in, const int* in_sizes, int n_in,
                              void* d_out, int out_size)
{
    const float* st    = (const float*)d_in[0];
    const float* Wq    = (const float*)d_in[1];
    const float* bq    = (const float*)d_in[2];
    const float* Wk    = (const float*)d_in[3];
    const float* bk    = (const float*)d_in[4];
    const float* Wv    = (const float*)d_in[5];
    const float* bv    = (const float*)d_in[6];
    const float* Wo    = (const float*)d_in[7];
    const float* bo    = (const float*)d_in[8];
    const float* ln1_g = (const float*)d_in[9];
    const float* ln1_b = (const float*)d_in[10];
    const float* fw    = (const float*)d_in[11];
    const float* Wf    = (const float*)d_in[12];
    const float* bf    = (const float*)d_in[13];
    const float* ln2_g = (const float*)d_in[14];
    const float* ln2_b = (const float*)d_in[15];
    float* out = (float*)d_out;

    void* sp = nullptr;
    cudaGetSymbolAddress(&sp, g_scratch);
    float* S = (float*)sp;

    dim3 blk(256);
    dim3 gBig(E_DIM / BN, NROWS / BM);     // (8, 384)
    dim3 gF(HID / BN, NTOK / BM);          // (8, 64)

    // QKV projections: (49152x1024) @ (1024x1024)^T
    sgemm_nt<<<gBig, blk>>>(st, Wq, bq, S + OFF_Q, NROWS, E_DIM, E_DIM, 0);
    sgemm_nt<<<gBig, blk>>>(st, Wk, bk, S + OFF_K, NROWS, E_DIM, E_DIM, 0);
    sgemm_nt<<<gBig, blk>>>(st, Wv, bv, S + OFF_V, NROWS, E_DIM, E_DIM, 0);

    // 6x6 attention per (token, head): 8192*16 warps, 8 warps/block
    attn6_kernel<<<(NTOK * H_HEADS) / 8, blk>>>(S + OFF_Q, S + OFF_K, S + OFF_V,
                                                S + OFF_C);

    // Output projection (writes over Q buffer)
    sgemm_nt<<<gBig, blk>>>(S + OFF_C, Wo, bo, S + OFF_O, NROWS, E_DIM, E_DIM, 0);

    // LN1(out + st) + weighted fusion over the 6 states -> F (8192x1024)
    ln1_fuse_kernel<<<NTOK, blk>>>(S + OFF_O, st, ln1_g, ln1_b, fw, S + OFF_F);

    // Final projection + bias + LeakyReLU -> H
    sgemm_nt<<<gF, blk>>>(S + OFF_F, Wf, bf, S + OFF_H, NTOK, HID, E_DIM, 1);

    // LN2 -> output
    ln2_kernel<<<NTOK, blk>>>(S + OFF_H, ln2_g, ln2_b, out);
}

// round 11
// speedup vs baseline: 2.3189x; 2.3189x over previous
#include <cuda_runtime.h>
#include <cuda_bf16.h>
#include <cstdint>
#include <cstddef>

// ---------------------------------------------------------------------------
// Problem constants
// ---------------------------------------------------------------------------
#define E_DIM   1024
#define H_HEADS 16
#define D_HEAD  64
#define NTOK    8192          // B*S = 16*512
#define NROWS   49152         // 6 * NTOK
#define HID     1024

// ---------------------------------------------------------------------------
// Scratch (no cudaMalloc allowed).
// ---------------------------------------------------------------------------
#define OFF_Q 0ull
#define OFF_K 50331648ull
#define OFF_V 100663296ull
#define OFF_C 150994944ull
#define OFF_O OFF_Q
#define OFF_F 201326592ull
#define OFF_H 209715200ull

__device__ float g_scratch[218103808];

// bf16 offsets (elements)
#define BOFF_STH  0ull
#define BOFF_STL  50331648ull
#define BOFF_CXH  100663296ull
#define BOFF_CXL  150994944ull
#define BOFF_FH   201326592ull
#define BOFF_FL   209715200ull
#define BOFF_W    218103808ull          // 10 x 1048576

__device__ __nv_bfloat16 g_bf[228589568];

// ---------------------------------------------------------------------------
// PTX helpers (sm_80-era instructions only: cp.async / ldmatrix / mma.sync)
// ---------------------------------------------------------------------------
__device__ __forceinline__ uint32_t smem_u32(const void* p) {
    uint32_t a;
    asm("{ .reg .u64 t; cvta.to.shared.u64 t, %1; cvt.u32.u64 %0, t; }"
        : "=r"(a) : "l"(p));
    return a;
}

#define CP_ASYNC16(dst, src) \
    asm volatile("cp.async.cg.shared.global [%0], [%1], 16;" \
                 :: "r"(dst), "l"(src) : "memory")
#define CP_COMMIT() asm volatile("cp.async.commit_group;" ::: "memory")
#define CP_WAIT0()  asm volatile("cp.async.wait_group 0;" ::: "memory")

__device__ __forceinline__ void ldsm4(uint32_t* r, uint32_t addr) {
    asm volatile("ldmatrix.sync.aligned.m8n8.x4.shared.b16 {%0,%1,%2,%3}, [%4];"
        : "=r"(r[0]), "=r"(r[1]), "=r"(r[2]), "=r"(r[3]) : "r"(addr));
}

__device__ __forceinline__ void mma16816(float* d, const uint32_t* a,
                                         uint32_t b0, uint32_t b1) {
    asm volatile(
        "mma.sync.aligned.m16n8k16.row.col.f32.bf16.bf16.f32 "
        "{%0,%1,%2,%3}, {%4,%5,%6,%7}, {%8,%9}, {%0,%1,%2,%3};"
        : "+f"(d[0]), "+f"(d[1]), "+f"(d[2]), "+f"(d[3])
        : "r"(a[0]), "r"(a[1]), "r"(a[2]), "r"(a[3]), "r"(b0), "r"(b1));
}

__device__ __forceinline__ uint32_t sw128(uint32_t off) {
    return off ^ ((off >> 3) & 0x70);
}

// ---------------------------------------------------------------------------
// Split-convert: fp32 -> (hi, lo) bf16, grid-stride over float4
// ---------------------------------------------------------------------------
__global__ __launch_bounds__(256)
void cvt_split(const float* __restrict__ src, __nv_bfloat16* __restrict__ hi,
               __nv_bfloat16* __restrict__ lo, int n4)
{
    for (int i = blockIdx.x * 256 + threadIdx.x; i < n4; i += gridDim.x * 256) {
        float4 x = ((const float4*)src)[i];
        __nv_bfloat16 h0 = __float2bfloat16(x.x);
        __nv_bfloat16 h1 = __float2bfloat16(x.y);
        __nv_bfloat16 h2 = __float2bfloat16(x.z);
        __nv_bfloat16 h3 = __float2bfloat16(x.w);
        __nv_bfloat16 l0 = __float2bfloat16(x.x - __bfloat162float(h0));
        __nv_bfloat16 l1 = __float2bfloat16(x.y - __bfloat162float(h1));
        __nv_bfloat16 l2 = __float2bfloat16(x.z - __bfloat162float(h2));
        __nv_bfloat16 l3 = __float2bfloat16(x.w - __bfloat162float(h3));
        ((__nv_bfloat162*)hi)[2 * i]     = __nv_bfloat162(h0, h1);
        ((__nv_bfloat162*)hi)[2 * i + 1] = __nv_bfloat162(h2, h3);
        ((__nv_bfloat162*)lo)[2 * i]     = __nv_bfloat162(l0, l1);
        ((__nv_bfloat162*)lo)[2 * i + 1] = __nv_bfloat162(l2, l3);
    }
}

// ---------------------------------------------------------------------------
// Tensor-core GEMM (NT): C[m,n] = sum_k A[m,k]*W[n,k] + bias[n], opt LeakyReLU
// A,W pre-split into bf16 hi/lo; acc = AhBh + AhBl + AlBh in fp32 (mma.sync).
// 128x128 CTA tile, 8 warps (2x4), 64x32 warp tile, K-chunks of 64 bf16.
// SW128-swizzled SMEM tiles, cp.async double buffering.
// ---------------------------------------------------------------------------
#define TILE_B      16384     // 128 rows x 128 bytes (64 bf16)
#define STAGE_BYTES 65536     // 4 tiles (Ah, Al, Bh, Bl)

__global__ __launch_bounds__(256, 1)
void gemm_bf16x3(const __nv_bfloat16* __restrict__ Ah, const __nv_bfloat16* __restrict__ Al,
                 const __nv_bfloat16* __restrict__ Bh, const __nv_bfloat16* __restrict__ Bl,
                 const float* __restrict__ bias, float* __restrict__ Cout,
                 int M, int N, int K, int act)
{
    extern __shared__ char smem_raw[];
    char* sm = (char*)(((uintptr_t)smem_raw + 1023) & ~(uintptr_t)1023);
    const uint32_t smb = smem_u32(sm);

    const int tid  = threadIdx.x;
    const int wid  = tid >> 5;
    const int lane = tid & 31;
    const int m0   = blockIdx.y * 128;
    const int n0   = blockIdx.x * 128;
    const int wm   = wid >> 2;       // 0..1
    const int wn   = wid & 3;        // 0..3

    float acc[4][4][4];
#pragma unroll
    for (int i = 0; i < 4; i++)
#pragma unroll
        for (int j = 0; j < 4; j++)
#pragma unroll
            for (int r = 0; r < 4; r++) acc[i][j][r] = 0.f;

    const int nchunk = K >> 6;

    // ---- async tile loader for chunk c ----
    auto issue_load = [&](int c) {
        const int stg = c & 1;
        const uint32_t sb = smb + stg * STAGE_BYTES;
        const int k0 = c << 6;
#pragma unroll
        for (int b = 0; b < 4; b++) {
            const __nv_bfloat16* src = (b == 0) ? Ah : (b == 1) ? Al
                                     : (b == 2) ? Bh : Bl;
            const int rb = (b < 2) ? m0 : n0;
            const uint32_t dstb = sb + b * TILE_B;
#pragma unroll
            for (int i = 0; i < 4; i++) {
                int idx = tid + i * 256;           // 0..1023 16B-slots
                int row = idx >> 3;
                int seg = idx & 7;
                const void* g = src + (size_t)(rb + row) * K + k0 + seg * 8;
                CP_ASYNC16(dstb + sw128(row * 128 + seg * 16), g);
            }
        }
        CP_COMMIT();
    };

    issue_load(0);

    const int lrow = lane & 15;
    const int lseg = lane >> 4;

    for (int c = 0; c < nchunk; c++) {
        CP_WAIT0();
        __syncthreads();
        if (c + 1 < nchunk) issue_load(c + 1);     // overlaps compute of c

        const uint32_t sb = smb + (c & 1) * STAGE_BYTES;
#pragma unroll
        for (int ks = 0; ks < 4; ks++) {
            const int kb = ks * 32 + lseg * 16;    // byte col for this lane

            uint32_t a[4][4], bH[2][4], bL[2][4];
#pragma unroll
            for (int fm = 0; fm < 4; fm++)
                ldsm4(a[fm], sb + sw128((wm * 64 + fm * 16 + lrow) * 128 + kb));
#pragma unroll
            for (int g = 0; g < 2; g++)
                ldsm4(bH[g], sb + 2 * TILE_B +
                             sw128((wn * 32 + g * 16 + lrow) * 128 + kb));
#pragma unroll
            for (int g = 0; g < 2; g++)
                ldsm4(bL[g], sb + 3 * TILE_B +
                             sw128((wn * 32 + g * 16 + lrow) * 128 + kb));

            // Ah*Bh + Ah*Bl
#pragma unroll
            for (int fm = 0; fm < 4; fm++)
#pragma unroll
                for (int nf = 0; nf < 4; nf++) {
                    mma16816(acc[fm][nf], a[fm],
                             bH[nf >> 1][nf & 1], bH[nf >> 1][(nf & 1) + 2]);
                    mma16816(acc[fm][nf], a[fm],
                             bL[nf >> 1][nf & 1], bL[nf >> 1][(nf & 1) + 2]);
                }

            // Al*Bh (reuse bH, overwrite a with Al fragments)
#pragma unroll
            for (int fm = 0; fm < 4; fm++)
                ldsm4(a[fm], sb + TILE_B +
                             sw128((wm * 64 + fm * 16 + lrow) * 128 + kb));
#pragma unroll
            for (int fm = 0; fm < 4; fm++)
#pragma unroll
                for (int nf = 0; nf < 4; nf++)
                    mma16816(acc[fm][nf], a[fm],
                             bH[nf >> 1][nf & 1], bH[nf >> 1][(nf & 1) + 2]);
        }
    }

    // ---- epilogue: direct fragment stores with bias (+LeakyReLU) ----
#pragma unroll
    for (int fm = 0; fm < 4; fm++) {
        const int r0 = m0 + wm * 64 + fm * 16 + (lane >> 2);
#pragma unroll
        for (int nf = 0; nf < 4; nf++) {
            const int col = n0 + wn * 32 + nf * 8 + (lane & 3) * 2;
            float2 bv = *(const float2*)(bias + col);
            float2 v0, v1;
            v0.x = acc[fm][nf][0] + bv.x;
            v0.y = acc[fm][nf][1] + bv.y;
            v1.x = acc[fm][nf][2] + bv.x;
            v1.y = acc[fm][nf][3] + bv.y;
            if (act) {
                v0.x = v0.x >= 0.f ? v0.x : 0.01f * v0.x;
                v0.y = v0.y >= 0.f ? v0.y : 0.01f * v0.y;
                v1.x = v1.x >= 0.f ? v1.x : 0.01f * v1.x;
                v1.y = v1.y >= 0.f ? v1.y : 0.01f * v1.y;
            }
            *(float2*)(Cout + (size_t)r0 * N + col)       = v0;
            *(float2*)(Cout + (size_t)(r0 + 8) * N + col) = v1;
        }
    }
}

// ---------------------------------------------------------------------------
// Tiny 6x6 attention: one warp per (token n, head h).
// ---------------------------------------------------------------------------
__device__ __forceinline__ float warpAllSum(float v)
{
#pragma unroll
    for (int o = 16; o; o >>= 1) v += __shfl_xor_sync(0xffffffffu, v, o);
    return v;
}

__global__ __launch_bounds__(256)
void attn6_kernel(const float* __restrict__ Q, const float* __restrict__ K,
                  const float* __restrict__ V, float* __restrict__ C)
{
    const int warp = threadIdx.x >> 5;
    const int lane = threadIdx.x & 31;
    const int idx  = blockIdx.x * 8 + warp;
    const int n = idx >> 4;
    const int h = idx & 15;

    const size_t base = (size_t)n * E_DIM + h * D_HEAD + 2 * lane;

    float2 q[6], k[6], v[6];
#pragma unroll
    for (int j = 0; j < 6; j++) {
        size_t off = base + (size_t)j * NTOK * E_DIM;
        q[j] = *(const float2*)(Q + off);
        k[j] = *(const float2*)(K + off);
        v[j] = *(const float2*)(V + off);
    }

    float s[6][6];
#pragma unroll
    for (int i = 0; i < 6; i++)
#pragma unroll
        for (int j = 0; j < 6; j++) {
            float p = q[i].x * k[j].x + q[i].y * k[j].y;
            s[i][j] = warpAllSum(p) * 0.125f;
        }

#pragma unroll
    for (int i = 0; i < 6; i++) {
        float mx = s[i][0];
#pragma unroll
        for (int j = 1; j < 6; j++) mx = fmaxf(mx, s[i][j]);
        float se = 0.f;
#pragma unroll
        for (int j = 0; j < 6; j++) { s[i][j] = __expf(s[i][j] - mx); se += s[i][j]; }
        float inv = 1.f / se;
#pragma unroll
        for (int j = 0; j < 6; j++) s[i][j] *= inv;
    }

#pragma unroll
    for (int i = 0; i < 6; i++) {
        float2 acc = make_float2(0.f, 0.f);
#pragma unroll
        for (int j = 0; j < 6; j++) {
            acc.x += s[i][j] * v[j].x;
            acc.y += s[i][j] * v[j].y;
        }
        *(float2*)(C + base + (size_t)i * NTOK * E_DIM) = acc;
    }
}

// ---------------------------------------------------------------------------
// Block-wide allreduce of (sum, sumsq)
// ---------------------------------------------------------------------------
__device__ __forceinline__ float2 blockAllReduce2(float2 v)
{
    __shared__ float2 sh[8];
    const int lane = threadIdx.x & 31;
    const int wid  = threadIdx.x >> 5;
#pragma unroll
    for (int o = 16; o; o >>= 1) {
        v.x += __shfl_xor_sync(0xffffffffu, v.x, o);
        v.y += __shfl_xor_sync(0xffffffffu, v.y, o);
    }
    if (lane == 0) sh[wid] = v;
    __syncthreads();
    if (wid == 0) {
        float2 t = (lane < 8) ? sh[lane] : make_float2(0.f, 0.f);
#pragma unroll
        for (int o = 4; o; o >>= 1) {
            t.x += __shfl_xor_sync(0xffffffffu, t.x, o);
            t.y += __shfl_xor_sync(0xffffffffu, t.y, o);
        }
        if (lane == 0) sh[0] = t;
    }
    __syncthreads();
    float2 r = sh[0];
    __syncthreads();
    return r;
}

// ---------------------------------------------------------------------------
// LN1(out + st) per (j, n) row, then weighted fusion over j -> F[n, 1024]
// ---------------------------------------------------------------------------
__global__ __launch_bounds__(256)
void ln1_fuse_kernel(const float* __restrict__ OP, const float* __restrict__ ST,
                     const float* __restrict__ g, const float* __restrict__ b,
                     const float* __restrict__ fw, float* __restrict__ F)
{
    const int n   = blockIdx.x;
    const int tid = threadIdx.x;

    float w[6];
    {
        float f[6], mx = -1e30f;
#pragma unroll
        for (int j = 0; j < 6; j++) { f[j] = fw[j]; mx = fmaxf(mx, f[j]); }
        float se = 0.f;
#pragma unroll
        for (int j = 0; j < 6; j++) { w[j] = expf(f[j] - mx); se += w[j]; }
        float inv = 1.f / se;
#pragma unroll
        for (int j = 0; j < 6; j++) w[j] *= inv;
    }

    float4 gg = ((const float4*)g)[tid];
    float4 bb = ((const float4*)b)[tid];
    float4 acc = make_float4(0.f, 0.f, 0.f, 0.f);

    for (int j = 0; j < 6; j++) {
        size_t roff = ((size_t)j * NTOK + n) * E_DIM;
        float4 x = ((const float4*)(OP + roff))[tid];
        float4 y = ((const float4*)(ST + roff))[tid];
        x.x += y.x; x.y += y.y; x.z += y.z; x.w += y.w;

        float2 r = make_float2(x.x + x.y + x.z + x.w,
                               x.x * x.x + x.y * x.y + x.z * x.z + x.w * x.w);
        r = blockAllReduce2(r);
        float mean = r.x * (1.f / 1024.f);
        float var  = r.y * (1.f / 1024.f) - mean * mean;
        float rstd = rsqrtf(var + 1e-5f);

        acc.x += w[j] * ((x.x - mean) * rstd * gg.x + bb.x);
        acc.y += w[j] * ((x.y - mean) * rstd * gg.y + bb.y);
        acc.z += w[j] * ((x.z - mean) * rstd * gg.z + bb.z);
        acc.w += w[j] * ((x.w - mean) * rstd * gg.w + bb.w);
    }
    ((float4*)F)[(size_t)n * 256 + tid] = acc;
}

// ---------------------------------------------------------------------------
// LN2 per token row
// ---------------------------------------------------------------------------
__global__ __launch_bounds__(256)
void ln2_kernel(const float* __restrict__ Hbuf, const float* __restrict__ g,
                const float* __restrict__ b, float* __restrict__ out)
{
    const int n   = blockIdx.x;
    const int tid = threadIdx.x;

    float4 x = ((const float4*)(Hbuf + (size_t)n * HID))[tid];
    float2 r = make_float2(x.x + x.y + x.z + x.w,
                           x.x * x.x + x.y * x.y + x.z * x.z + x.w * x.w);
    r = blockAllReduce2(r);
    float mean = r.x * (1.f / 1024.f);
    float var  = r.y * (1.f / 1024.f) - mean * mean;
    float rstd = rsqrtf(var + 1e-5f);

    float4 gg = ((const float4*)g)[tid];
    float4 bb = ((const float4*)b)[tid];
    float4 o;
    o.x = (x.x - mean) * rstd * gg.x + bb.x;
    o.y = (x.y - mean) * rstd * gg.y + bb.y;
    o.z = (x.z - mean) * rstd * gg.z + bb.z;
    o.w = (x.w - mean) * rstd * gg.w + bb.w;
    ((float4*)(out + (size_t)n * HID))[tid] = o;
}

// ---------------------------------------------------------------------------
// Launch
// ---------------------------------------------------------------------------
extern "C" void kernel_launch(void* const* d_in, const int* in_sizes, int n_in,
                              void* d_out, int out_size)
{
    const float* st    = (const float*)d_in[0];
    const float* Wq    = (const float*)d_in[1];
    const float* bq    = (const float*)d_in[2];
    const float* Wk    = (const float*)d_in[3];
    const float* bk    = (const float*)d_in[4];
    const float* Wv    = (const float*)d_in[5];
    const float* bv    = (const float*)d_in[6];
    const float* Wo    = (const float*)d_in[7];
    const float* bo    = (const float*)d_in[8];
    const float* ln1_g = (const float*)d_in[9];
    const float* ln1_b = (const float*)d_in[10];
    const float* fw    = (const float*)d_in[11];
    const float* Wf    = (const float*)d_in[12];
    const float* bf    = (const float*)d_in[13];
    const float* ln2_g = (const float*)d_in[14];
    const float* ln2_b = (const float*)d_in[15];
    float* out = (float*)d_out;

    void* sp = nullptr;
    cudaGetSymbolAddress(&sp, g_scratch);
    float* S = (float*)sp;
    void* bp = nullptr;
    cudaGetSymbolAddress(&bp, g_bf);
    __nv_bfloat16* BF = (__nv_bfloat16*)bp;

    const int GSM = 2 * STAGE_BYTES + 1024;   // 132096
    cudaFuncSetAttribute(gemm_bf16x3,
                         cudaFuncAttributeMaxDynamicSharedMemorySize, GSM);

    dim3 blk(256);
    dim3 gBig(E_DIM / 128, NROWS / 128);   // (8, 384)
    dim3 gF(HID / 128, NTOK / 128);        // (8, 64)

    __nv_bfloat16* stH = BF + BOFF_STH;
    __nv_bfloat16* stL = BF + BOFF_STL;
    __nv_bfloat16* cxH = BF + BOFF_CXH;
    __nv_bfloat16* cxL = BF + BOFF_CXL;
    __nv_bfloat16* fH  = BF + BOFF_FH;
    __nv_bfloat16* fL  = BF + BOFF_FL;
    __nv_bfloat16* wB  = BF + BOFF_W;      // 10 x 1048576

    // split-convert the shared activation input and the five weight matrices
    cvt_split<<<2048, blk>>>(st, stH, stL, NROWS * E_DIM / 4);
    cvt_split<<<256, blk>>>(Wq, wB + 0 * 1048576, wB + 1 * 1048576, 262144);
    cvt_split<<<256, blk>>>(Wk, wB + 2 * 1048576, wB + 3 * 1048576, 262144);
    cvt_split<<<256, blk>>>(Wv, wB + 4 * 1048576, wB + 5 * 1048576, 262144);
    cvt_split<<<256, blk>>>(Wo, wB + 6 * 1048576, wB + 7 * 1048576, 262144);
    cvt_split<<<256, blk>>>(Wf, wB + 8 * 1048576, wB + 9 * 1048576, 262144);

    // Q/K/V projections (tensor cores, bf16x3)
    gemm_bf16x3<<<gBig, blk, GSM>>>(stH, stL, wB + 0 * 1048576, wB + 1 * 1048576,
                                    bq, S + OFF_Q, NROWS, E_DIM, E_DIM, 0);
    gemm_bf16x3<<<gBig, blk, GSM>>>(stH, stL, wB + 2 * 1048576, wB + 3 * 1048576,
                                    bk, S + OFF_K, NROWS, E_DIM, E_DIM, 0);
    gemm_bf16x3<<<gBig, blk, GSM>>>(stH, stL, wB + 4 * 1048576, wB + 5 * 1048576,
                                    bv, S + OFF_V, NROWS, E_DIM, E_DIM, 0);

    // tiny attention
    attn6_kernel<<<(NTOK * H_HEADS) / 8, blk>>>(S + OFF_Q, S + OFF_K, S + OFF_V,
                                                S + OFF_C);

    // output projection
    cvt_split<<<2048, blk>>>(S + OFF_C, cxH, cxL, NROWS * E_DIM / 4);
    gemm_bf16x3<<<gBig, blk, GSM>>>(cxH, cxL, wB + 6 * 1048576, wB + 7 * 1048576,
                                    bo, S + OFF_O, NROWS, E_DIM, E_DIM, 0);

    // LN1 + fusion
    ln1_fuse_kernel<<<NTOK, blk>>>(S + OFF_O, st, ln1_g, ln1_b, fw, S + OFF_F);

    // final projection + LeakyReLU
    cvt_split<<<512, blk>>>(S + OFF_F, fH, fL, NTOK * HID / 4);
    gemm_bf16x3<<<gF, blk, GSM>>>(fH, fL, wB + 8 * 1048576, wB + 9 * 1048576,
                                  bf, S + OFF_H, NTOK, HID, E_DIM, 1);

    // LN2
    ln2_kernel<<<NTOK, blk>>>(S + OFF_H, ln2_g, ln2_b, out);
}

// round 13
// speedup vs baseline: 2.4967x; 1.0766x over previous
#include <cuda_runtime.h>
#include <cuda_bf16.h>
#include <cstdint>
#include <cstddef>

// ---------------------------------------------------------------------------
// Problem constants
// ---------------------------------------------------------------------------
#define E_DIM   1024
#define H_HEADS 16
#define D_HEAD  64
#define NTOK    8192          // B*S = 16*512
#define NROWS   49152         // 6 * NTOK
#define HID     1024

// ---------------------------------------------------------------------------
// Scratch (no cudaMalloc allowed).
// ---------------------------------------------------------------------------
#define OFF_Q 0ull
#define OFF_K 50331648ull
#define OFF_V 100663296ull
#define OFF_O OFF_Q
#define OFF_H 209715200ull

__device__ float g_scratch[218103808];

// bf16 offsets (elements)
#define BOFF_STH  0ull
#define BOFF_STL  50331648ull
#define BOFF_CXH  100663296ull
#define BOFF_CXL  150994944ull
#define BOFF_FH   201326592ull
#define BOFF_FL   209715200ull
#define BOFF_W    218103808ull          // 10 x 1048576

__device__ __nv_bfloat16 g_bf[228589568];

// ---------------------------------------------------------------------------
// PTX helpers (sm_80-era instructions only: cp.async / ldmatrix / mma.sync)
// ---------------------------------------------------------------------------
__device__ __forceinline__ uint32_t smem_u32(const void* p) {
    uint32_t a;
    asm("{ .reg .u64 t; cvta.to.shared.u64 t, %1; cvt.u32.u64 %0, t; }"
        : "=r"(a) : "l"(p));
    return a;
}

#define CP_ASYNC16(dst, src) \
    asm volatile("cp.async.cg.shared.global [%0], [%1], 16;" \
                 :: "r"(dst), "l"(src) : "memory")
#define CP_COMMIT() asm volatile("cp.async.commit_group;" ::: "memory")
#define CP_WAIT0()  asm volatile("cp.async.wait_group 0;" ::: "memory")
#define CP_WAIT1()  asm volatile("cp.async.wait_group 1;" ::: "memory")

__device__ __forceinline__ void ldsm4(uint32_t* r, uint32_t addr) {
    asm volatile("ldmatrix.sync.aligned.m8n8.x4.shared.b16 {%0,%1,%2,%3}, [%4];"
        : "=r"(r[0]), "=r"(r[1]), "=r"(r[2]), "=r"(r[3]) : "r"(addr));
}

__device__ __forceinline__ void mma16816(float* d, const uint32_t* a,
                                         uint32_t b0, uint32_t b1) {
    asm volatile(
        "mma.sync.aligned.m16n8k16.row.col.f32.bf16.bf16.f32 "
        "{%0,%1,%2,%3}, {%4,%5,%6,%7}, {%8,%9}, {%0,%1,%2,%3};"
        : "+f"(d[0]), "+f"(d[1]), "+f"(d[2]), "+f"(d[3])
        : "r"(a[0]), "r"(a[1]), "r"(a[2]), "r"(a[3]), "r"(b0), "r"(b1));
}

__device__ __forceinline__ uint32_t sw128(uint32_t off) {
    return off ^ ((off >> 3) & 0x70);
}

// ---------------------------------------------------------------------------
// Split-convert: fp32 -> (hi, lo) bf16, grid-stride over float4
// ---------------------------------------------------------------------------
__global__ __launch_bounds__(256)
void cvt_split(const float* __restrict__ src, __nv_bfloat16* __restrict__ hi,
               __nv_bfloat16* __restrict__ lo, int n4)
{
    for (int i = blockIdx.x * 256 + threadIdx.x; i < n4; i += gridDim.x * 256) {
        float4 x = ((const float4*)src)[i];
        __nv_bfloat16 h0 = __float2bfloat16(x.x);
        __nv_bfloat16 h1 = __float2bfloat16(x.y);
        __nv_bfloat16 h2 = __float2bfloat16(x.z);
        __nv_bfloat16 h3 = __float2bfloat16(x.w);
        __nv_bfloat16 l0 = __float2bfloat16(x.x - __bfloat162float(h0));
        __nv_bfloat16 l1 = __float2bfloat16(x.y - __bfloat162float(h1));
        __nv_bfloat16 l2 = __float2bfloat16(x.z - __bfloat162float(h2));
        __nv_bfloat16 l3 = __float2bfloat16(x.w - __bfloat162float(h3));
        ((__nv_bfloat162*)hi)[2 * i]     = __nv_bfloat162(h0, h1);
        ((__nv_bfloat162*)hi)[2 * i + 1] = __nv_bfloat162(h2, h3);
        ((__nv_bfloat162*)lo)[2 * i]     = __nv_bfloat162(l0, l1);
        ((__nv_bfloat162*)lo)[2 * i + 1] = __nv_bfloat162(l2, l3);
    }
}

// ---------------------------------------------------------------------------
// Tensor-core GEMM (NT): C[m,n] = sum_k A[m,k]*W[n,k] + bias[n], opt LeakyReLU
// A,W pre-split into bf16 hi/lo; acc = AhBh + AhBl + AlBh in fp32 (mma.sync).
// 128x128 CTA tile, 16 warps (4x4), 32x32 warp tile, K-chunks of 64 bf16.
// SW128-swizzled SMEM, 3-stage cp.async pipeline.
// ---------------------------------------------------------------------------
#define TILE_B      16384     // 128 rows x 128 bytes (64 bf16)
#define STAGE_BYTES 65536     // 4 tiles (Ah, Al, Bh, Bl)
#define NSTAGE      3

__global__ __launch_bounds__(512, 1)
void gemm_bf16x3(const __nv_bfloat16* __restrict__ Ah, const __nv_bfloat16* __restrict__ Al,
                 const __nv_bfloat16* __restrict__ Bh, const __nv_bfloat16* __restrict__ Bl,
                 const float* __restrict__ bias, float* __restrict__ Cout,
                 int M, int N, int K, int act)
{
    extern __shared__ char smem_raw[];
    char* sm = (char*)(((uintptr_t)smem_raw + 1023) & ~(uintptr_t)1023);
    const uint32_t smb = smem_u32(sm);

    const int tid  = threadIdx.x;
    const int wid  = tid >> 5;
    const int lane = tid & 31;
    const int m0   = blockIdx.y * 128;
    const int n0   = blockIdx.x * 128;
    const int wm   = wid >> 2;       // 0..3
    const int wn   = wid & 3;        // 0..3

    float acc[2][4][4];
#pragma unroll
    for (int i = 0; i < 2; i++)
#pragma unroll
        for (int j = 0; j < 4; j++)
#pragma unroll
            for (int r = 0; r < 4; r++) acc[i][j][r] = 0.f;

    const int nchunk = K >> 6;

    // ---- async tile loader for chunk c (stage = c % 3) ----
    auto issue_load = [&](int c) {
        const uint32_t sb = smb + (c % NSTAGE) * STAGE_BYTES;
        const int k0 = c << 6;
#pragma unroll
        for (int b = 0; b < 4; b++) {
            const __nv_bfloat16* src = (b == 0) ? Ah : (b == 1) ? Al
                                     : (b == 2) ? Bh : Bl;
            const int rb = (b < 2) ? m0 : n0;
            const uint32_t dstb = sb + b * TILE_B;
#pragma unroll
            for (int i = 0; i < 2; i++) {
                int idx = tid + i * 512;           // 0..1023 16B-slots
                int row = idx >> 3;
                int seg = idx & 7;
                const void* g = src + (size_t)(rb + row) * K + k0 + seg * 8;
                CP_ASYNC16(dstb + sw128(row * 128 + seg * 16), g);
            }
        }
        CP_COMMIT();
    };

    issue_load(0);
    if (nchunk > 1) issue_load(1);

    const int lrow = lane & 15;
    const int lseg = lane >> 4;

    for (int c = 0; c < nchunk; c++) {
        if (c + 1 < nchunk) { CP_WAIT1(); } else { CP_WAIT0(); }
        __syncthreads();
        if (c + 2 < nchunk) issue_load(c + 2);

        const uint32_t sb = smb + (c % NSTAGE) * STAGE_BYTES;
#pragma unroll
        for (int ks = 0; ks < 4; ks++) {
            const int kb = ks * 32 + lseg * 16;

            uint32_t a[2][4], bH[2][4], bL[2][4];
#pragma unroll
            for (int fm = 0; fm < 2; fm++)
                ldsm4(a[fm], sb + sw128((wm * 32 + fm * 16 + lrow) * 128 + kb));
#pragma unroll
            for (int g = 0; g < 2; g++)
                ldsm4(bH[g], sb + 2 * TILE_B +
                             sw128((wn * 32 + g * 16 + lrow) * 128 + kb));
#pragma unroll
            for (int g = 0; g < 2; g++)
                ldsm4(bL[g], sb + 3 * TILE_B +
                             sw128((wn * 32 + g * 16 + lrow) * 128 + kb));

            // Ah*Bh + Ah*Bl
#pragma unroll
            for (int fm = 0; fm < 2; fm++)
#pragma unroll
                for (int nf = 0; nf < 4; nf++) {
                    mma16816(acc[fm][nf], a[fm],
                             bH[nf >> 1][nf & 1], bH[nf >> 1][(nf & 1) + 2]);
                    mma16816(acc[fm][nf], a[fm],
                             bL[nf >> 1][nf & 1], bL[nf >> 1][(nf & 1) + 2]);
                }

            // Al*Bh (reuse bH, overwrite a with Al fragments)
#pragma unroll
            for (int fm = 0; fm < 2; fm++)
                ldsm4(a[fm], sb + TILE_B +
                             sw128((wm * 32 + fm * 16 + lrow) * 128 + kb));
#pragma unroll
            for (int fm = 0; fm < 2; fm++)
#pragma unroll
                for (int nf = 0; nf < 4; nf++)
                    mma16816(acc[fm][nf], a[fm],
                             bH[nf >> 1][nf & 1], bH[nf >> 1][(nf & 1) + 2]);
        }
    }

    // ---- epilogue: direct fragment stores with bias (+LeakyReLU) ----
#pragma unroll
    for (int fm = 0; fm < 2; fm++) {
        const int r0 = m0 + wm * 32 + fm * 16 + (lane >> 2);
#pragma unroll
        for (int nf = 0; nf < 4; nf++) {
            const int col = n0 + wn * 32 + nf * 8 + (lane & 3) * 2;
            float2 bv = *(const float2*)(bias + col);
            float2 v0, v1;
            v0.x = acc[fm][nf][0] + bv.x;
            v0.y = acc[fm][nf][1] + bv.y;
            v1.x = acc[fm][nf][2] + bv.x;
            v1.y = acc[fm][nf][3] + bv.y;
            if (act) {
                v0.x = v0.x >= 0.f ? v0.x : 0.01f * v0.x;
                v0.y = v0.y >= 0.f ? v0.y : 0.01f * v0.y;
                v1.x = v1.x >= 0.f ? v1.x : 0.01f * v1.x;
                v1.y = v1.y >= 0.f ? v1.y : 0.01f * v1.y;
            }
            *(float2*)(Cout + (size_t)r0 * N + col)       = v0;
            *(float2*)(Cout + (size_t)(r0 + 8) * N + col) = v1;
        }
    }
}

// ---------------------------------------------------------------------------
// Tiny 6x6 attention: one warp per (token n, head h).
// Emits context directly as split hi/lo bf16 for the O-projection GEMM.
// ---------------------------------------------------------------------------
__device__ __forceinline__ float warpAllSum(float v)
{
#pragma unroll
    for (int o = 16; o; o >>= 1) v += __shfl_xor_sync(0xffffffffu, v, o);
    return v;
}

__global__ __launch_bounds__(256)
void attn6_kernel(const float* __restrict__ Q, const float* __restrict__ K,
                  const float* __restrict__ V,
                  __nv_bfloat16* __restrict__ CH, __nv_bfloat16* __restrict__ CL)
{
    const int warp = threadIdx.x >> 5;
    const int lane = threadIdx.x & 31;
    const int idx  = blockIdx.x * 8 + warp;
    const int n = idx >> 4;
    const int h = idx & 15;

    const size_t base = (size_t)n * E_DIM + h * D_HEAD + 2 * lane;

    float2 q[6], k[6], v[6];
#pragma unroll
    for (int j = 0; j < 6; j++) {
        size_t off = base + (size_t)j * NTOK * E_DIM;
        q[j] = *(const float2*)(Q + off);
        k[j] = *(const float2*)(K + off);
        v[j] = *(const float2*)(V + off);
    }

    float s[6][6];
#pragma unroll
    for (int i = 0; i < 6; i++)
#pragma unroll
        for (int j = 0; j < 6; j++) {
            float p = q[i].x * k[j].x + q[i].y * k[j].y;
            s[i][j] = warpAllSum(p) * 0.125f;
        }

#pragma unroll
    for (int i = 0; i < 6; i++) {
        float mx = s[i][0];
#pragma unroll
        for (int j = 1; j < 6; j++) mx = fmaxf(mx, s[i][j]);
        float se = 0.f;
#pragma unroll
        for (int j = 0; j < 6; j++) { s[i][j] = __expf(s[i][j] - mx); se += s[i][j]; }
        float inv = 1.f / se;
#pragma unroll
        for (int j = 0; j < 6; j++) s[i][j] *= inv;
    }

#pragma unroll
    for (int i = 0; i < 6; i++) {
        float2 acc = make_float2(0.f, 0.f);
#pragma unroll
        for (int j = 0; j < 6; j++) {
            acc.x += s[i][j] * v[j].x;
            acc.y += s[i][j] * v[j].y;
        }
        __nv_bfloat16 h0 = __float2bfloat16(acc.x);
        __nv_bfloat16 h1 = __float2bfloat16(acc.y);
        __nv_bfloat16 l0 = __float2bfloat16(acc.x - __bfloat162float(h0));
        __nv_bfloat16 l1 = __float2bfloat16(acc.y - __bfloat162float(h1));
        size_t off = base + (size_t)i * NTOK * E_DIM;
        *(__nv_bfloat162*)(CH + off) = __nv_bfloat162(h0, h1);
        *(__nv_bfloat162*)(CL + off) = __nv_bfloat162(l0, l1);
    }
}

// ---------------------------------------------------------------------------
// Block-wide allreduce of (sum, sumsq)
// ---------------------------------------------------------------------------
__device__ __forceinline__ float2 blockAllReduce2(float2 v)
{
    __shared__ float2 sh[8];
    const int lane = threadIdx.x & 31;
    const int wid  = threadIdx.x >> 5;
#pragma unroll
    for (int o = 16; o; o >>= 1) {
        v.x += __shfl_xor_sync(0xffffffffu, v.x, o);
        v.y += __shfl_xor_sync(0xffffffffu, v.y, o);
    }
    if (lane == 0) sh[wid] = v;
    __syncthreads();
    if (wid == 0) {
        float2 t = (lane < 8) ? sh[lane] : make_float2(0.f, 0.f);
#pragma unroll
        for (int o = 4; o; o >>= 1) {
            t.x += __shfl_xor_sync(0xffffffffu, t.x, o);
            t.y += __shfl_xor_sync(0xffffffffu, t.y, o);
        }
        if (lane == 0) sh[0] = t;
    }
    __syncthreads();
    float2 r = sh[0];
    __syncthreads();
    return r;
}

// ---------------------------------------------------------------------------
// LN1(out + st) per (j, n) row, then weighted fusion over j.
// Emits the fused row directly as split hi/lo bf16 for the final GEMM.
// ---------------------------------------------------------------------------
__global__ __launch_bounds__(256)
void ln1_fuse_kernel(const float* __restrict__ OP, const float* __restrict__ ST,
                     const float* __restrict__ g, const float* __restrict__ b,
                     const float* __restrict__ fw,
                     __nv_bfloat16* __restrict__ FH, __nv_bfloat16* __restrict__ FL)
{
    const int n   = blockIdx.x;
    const int tid = threadIdx.x;

    float w[6];
    {
        float f[6], mx = -1e30f;
#pragma unroll
        for (int j = 0; j < 6; j++) { f[j] = fw[j]; mx = fmaxf(mx, f[j]); }
        float se = 0.f;
#pragma unroll
        for (int j = 0; j < 6; j++) { w[j] = expf(f[j] - mx); se += w[j]; }
        float inv = 1.f / se;
#pragma unroll
        for (int j = 0; j < 6; j++) w[j] *= inv;
    }

    float4 gg = ((const float4*)g)[tid];
    float4 bb = ((const float4*)b)[tid];
    float4 acc = make_float4(0.f, 0.f, 0.f, 0.f);

    for (int j = 0; j < 6; j++) {
        size_t roff = ((size_t)j * NTOK + n) * E_DIM;
        float4 x = ((const float4*)(OP + roff))[tid];
        float4 y = ((const float4*)(ST + roff))[tid];
        x.x += y.x; x.y += y.y; x.z += y.z; x.w += y.w;

        float2 r = make_float2(x.x + x.y + x.z + x.w,
                               x.x * x.x + x.y * x.y + x.z * x.z + x.w * x.w);
        r = blockAllReduce2(r);
        float mean = r.x * (1.f / 1024.f);
        float var  = r.y * (1.f / 1024.f) - mean * mean;
        float rstd = rsqrtf(var + 1e-5f);

        acc.x += w[j] * ((x.x - mean) * rstd * gg.x + bb.x);
        acc.y += w[j] * ((x.y - mean) * rstd * gg.y + bb.y);
        acc.z += w[j] * ((x.z - mean) * rstd * gg.z + bb.z);
        acc.w += w[j] * ((x.w - mean) * rstd * gg.w + bb.w);
    }

    __nv_bfloat16 h0 = __float2bfloat16(acc.x);
    __nv_bfloat16 h1 = __float2bfloat16(acc.y);
    __nv_bfloat16 h2 = __float2bfloat16(acc.z);
    __nv_bfloat16 h3 = __float2bfloat16(acc.w);
    __nv_bfloat16 l0 = __float2bfloat16(acc.x - __bfloat162float(h0));
    __nv_bfloat16 l1 = __float2bfloat16(acc.y - __bfloat162float(h1));
    __nv_bfloat16 l2 = __float2bfloat16(acc.z - __bfloat162float(h2));
    __nv_bfloat16 l3 = __float2bfloat16(acc.w - __bfloat162float(h3));
    size_t o2 = (size_t)n * 512 + 2 * tid;
    ((__nv_bfloat162*)FH)[o2]     = __nv_bfloat162(h0, h1);
    ((__nv_bfloat162*)FH)[o2 + 1] = __nv_bfloat162(h2, h3);
    ((__nv_bfloat162*)FL)[o2]     = __nv_bfloat162(l0, l1);
    ((__nv_bfloat162*)FL)[o2 + 1] = __nv_bfloat162(l2, l3);
}

// ---------------------------------------------------------------------------
// LN2 per token row
// ---------------------------------------------------------------------------
__global__ __launch_bounds__(256)
void ln2_kernel(const float* __restrict__ Hbuf, const float* __restrict__ g,
                const float* __restrict__ b, float* __restrict__ out)
{
    const int n   = blockIdx.x;
    const int tid = threadIdx.x;

    float4 x = ((const float4*)(Hbuf + (size_t)n * HID))[tid];
    float2 r = make_float2(x.x + x.y + x.z + x.w,
                           x.x * x.x + x.y * x.y + x.z * x.z + x.w * x.w);
    r = blockAllReduce2(r);
    float mean = r.x * (1.f / 1024.f);
    float var  = r.y * (1.f / 1024.f) - mean * mean;
    float rstd = rsqrtf(var + 1e-5f);

    float4 gg = ((const float4*)g)[tid];
    float4 bb = ((const float4*)b)[tid];
    float4 o;
    o.x = (x.x - mean) * rstd * gg.x + bb.x;
    o.y = (x.y - mean) * rstd * gg.y + bb.y;
    o.z = (x.z - mean) * rstd * gg.z + bb.z;
    o.w = (x.w - mean) * rstd * gg.w + bb.w;
    ((float4*)(out + (size_t)n * HID))[tid] = o;
}

// ---------------------------------------------------------------------------
// Launch
// ---------------------------------------------------------------------------
extern "C" void kernel_launch(void* const* d_in, const int* in_sizes, int n_in,
                              void* d_out, int out_size)
{
    const float* st    = (const float*)d_in[0];
    const float* Wq    = (const float*)d_in[1];
    const float* bq    = (const float*)d_in[2];
    const float* Wk    = (const float*)d_in[3];
    const float* bk    = (const float*)d_in[4];
    const float* Wv    = (const float*)d_in[5];
    const float* bv    = (const float*)d_in[6];
    const float* Wo    = (const float*)d_in[7];
    const float* bo    = (const float*)d_in[8];
    const float* ln1_g = (const float*)d_in[9];
    const float* ln1_b = (const float*)d_in[10];
    const float* fw    = (const float*)d_in[11];
    const float* Wf    = (const float*)d_in[12];
    const float* bf    = (const float*)d_in[13];
    const float* ln2_g = (const float*)d_in[14];
    const float* ln2_b = (const float*)d_in[15];
    float* out = (float*)d_out;

    void* sp = nullptr;
    cudaGetSymbolAddress(&sp, g_scratch);
    float* S = (float*)sp;
    void* bp = nullptr;
    cudaGetSymbolAddress(&bp, g_bf);
    __nv_bfloat16* BF = (__nv_bfloat16*)bp;

    const int GSM = NSTAGE * STAGE_BYTES + 1024;   // 197632
    cudaFuncSetAttribute(gemm_bf16x3,
                         cudaFuncAttributeMaxDynamicSharedMemorySize, GSM);

    dim3 blk(256);
    dim3 gblk(512);
    dim3 gBig(E_DIM / 128, NROWS / 128);   // (8, 384)
    dim3 gF(HID / 128, NTOK / 128);        // (8, 64)

    __nv_bfloat16* stH = BF + BOFF_STH;
    __nv_bfloat16* stL = BF + BOFF_STL;
    __nv_bfloat16* cxH = BF + BOFF_CXH;
    __nv_bfloat16* cxL = BF + BOFF_CXL;
    __nv_bfloat16* fH  = BF + BOFF_FH;
    __nv_bfloat16* fL  = BF + BOFF_FL;
    __nv_bfloat16* wB  = BF + BOFF_W;      // 10 x 1048576

    // split-convert the shared activation input and the five weight matrices
    cvt_split<<<2048, blk>>>(st, stH, stL, NROWS * E_DIM / 4);
    cvt_split<<<256, blk>>>(Wq, wB + 0 * 1048576, wB + 1 * 1048576, 262144);
    cvt_split<<<256, blk>>>(Wk, wB + 2 * 1048576, wB + 3 * 1048576, 262144);
    cvt_split<<<256, blk>>>(Wv, wB + 4 * 1048576, wB + 5 * 1048576, 262144);
    cvt_split<<<256, blk>>>(Wo, wB + 6 * 1048576, wB + 7 * 1048576, 262144);
    cvt_split<<<256, blk>>>(Wf, wB + 8 * 1048576, wB + 9 * 1048576, 262144);

    // Q/K/V projections (tensor cores, bf16x3)
    gemm_bf16x3<<<gBig, gblk, GSM>>>(stH, stL, wB + 0 * 1048576, wB + 1 * 1048576,
                                     bq, S + OFF_Q, NROWS, E_DIM, E_DIM, 0);
    gemm_bf16x3<<<gBig, gblk, GSM>>>(stH, stL, wB + 2 * 1048576, wB + 3 * 1048576,
                                     bk, S + OFF_K, NROWS, E_DIM, E_DIM, 0);
    gemm_bf16x3<<<gBig, gblk, GSM>>>(stH, stL, wB + 4 * 1048576, wB + 5 * 1048576,
                                     bv, S + OFF_V, NROWS, E_DIM, E_DIM, 0);

    // tiny attention -> split bf16 context
    attn6_kernel<<<(NTOK * H_HEADS) / 8, blk>>>(S + OFF_Q, S + OFF_K, S + OFF_V,
                                                cxH, cxL);

    // output projection
    gemm_bf16x3<<<gBig, gblk, GSM>>>(cxH, cxL, wB + 6 * 1048576, wB + 7 * 1048576,
                                     bo, S + OFF_O, NROWS, E_DIM, E_DIM, 0);

    // LN1 + fusion -> split bf16 fused rows
    ln1_fuse_kernel<<<NTOK, blk>>>(S + OFF_O, st, ln1_g, ln1_b, fw, fH, fL);

    // final projection + LeakyReLU
    gemm_bf16x3<<<gF, gblk, GSM>>>(fH, fL, wB + 8 * 1048576, wB + 9 * 1048576,
                                   bf, S + OFF_H, NTOK, HID, E_DIM, 1);

    // LN2
    ln2_kernel<<<NTOK, blk>>>(S + OFF_H, ln2_g, ln2_b, out);
}

// round 14
// speedup vs baseline: 2.4968x; 1.0001x over previous
#include <cuda_runtime.h>
#include <cuda_bf16.h>
#include <cstdint>
#include <cstddef>

// ---------------------------------------------------------------------------
// Problem constants
// ---------------------------------------------------------------------------
#define E_DIM   1024
#define H_HEADS 16
#define D_HEAD  64
#define NTOK    8192          // B*S = 16*512
#define NROWS   49152         // 6 * NTOK
#define HID     1024

// ---------------------------------------------------------------------------
// Scratch (no cudaMalloc allowed).
// ---------------------------------------------------------------------------
#define OFF_Q 0ull
#define OFF_K 50331648ull
#define OFF_V 100663296ull
#define OFF_O OFF_Q
#define OFF_H 209715200ull

__device__ float g_scratch[218103808];

// bf16 offsets (elements)
#define BOFF_STH  0ull
#define BOFF_STL  50331648ull
#define BOFF_CXH  100663296ull
#define BOFF_CXL  150994944ull
#define BOFF_FH   201326592ull
#define BOFF_FL   209715200ull
#define BOFF_W    218103808ull          // 10 x 1048576

__device__ __nv_bfloat16 g_bf[228589568];

// ---------------------------------------------------------------------------
// PTX helpers (sm_80-era instructions only: cp.async / ldmatrix / mma.sync)
// ---------------------------------------------------------------------------
__device__ __forceinline__ uint32_t smem_u32(const void* p) {
    uint32_t a;
    asm("{ .reg .u64 t; cvta.to.shared.u64 t, %1; cvt.u32.u64 %0, t; }"
        : "=r"(a) : "l"(p));
    return a;
}

#define CP_ASYNC16(dst, src) \
    asm volatile("cp.async.cg.shared.global [%0], [%1], 16;" \
                 :: "r"(dst), "l"(src) : "memory")
#define CP_COMMIT() asm volatile("cp.async.commit_group;" ::: "memory")
#define CP_WAIT0()  asm volatile("cp.async.wait_group 0;" ::: "memory")
#define CP_WAIT1()  asm volatile("cp.async.wait_group 1;" ::: "memory")

__device__ __forceinline__ void ldsm4(uint32_t* r, uint32_t addr) {
    asm volatile("ldmatrix.sync.aligned.m8n8.x4.shared.b16 {%0,%1,%2,%3}, [%4];"
        : "=r"(r[0]), "=r"(r[1]), "=r"(r[2]), "=r"(r[3]) : "r"(addr));
}

__device__ __forceinline__ void mma16816(float* d, const uint32_t* a,
                                         uint32_t b0, uint32_t b1) {
    asm volatile(
        "mma.sync.aligned.m16n8k16.row.col.f32.bf16.bf16.f32 "
        "{%0,%1,%2,%3}, {%4,%5,%6,%7}, {%8,%9}, {%0,%1,%2,%3};"
        : "+f"(d[0]), "+f"(d[1]), "+f"(d[2]), "+f"(d[3])
        : "r"(a[0]), "r"(a[1]), "r"(a[2]), "r"(a[3]), "r"(b0), "r"(b1));
}

__device__ __forceinline__ uint32_t sw128(uint32_t off) {
    return off ^ ((off >> 3) & 0x70);
}

// ---------------------------------------------------------------------------
// Split-convert: fp32 -> (hi, lo) bf16, grid-stride over float4
// ---------------------------------------------------------------------------
__global__ __launch_bounds__(256)
void cvt_split(const float* __restrict__ src, __nv_bfloat16* __restrict__ hi,
               __nv_bfloat16* __restrict__ lo, int n4)
{
    for (int i = blockIdx.x * 256 + threadIdx.x; i < n4; i += gridDim.x * 256) {
        float4 x = ((const float4*)src)[i];
        __nv_bfloat16 h0 = __float2bfloat16(x.x);
        __nv_bfloat16 h1 = __float2bfloat16(x.y);
        __nv_bfloat16 h2 = __float2bfloat16(x.z);
        __nv_bfloat16 h3 = __float2bfloat16(x.w);
        __nv_bfloat16 l0 = __float2bfloat16(x.x - __bfloat162float(h0));
        __nv_bfloat16 l1 = __float2bfloat16(x.y - __bfloat162float(h1));
        __nv_bfloat16 l2 = __float2bfloat16(x.z - __bfloat162float(h2));
        __nv_bfloat16 l3 = __float2bfloat16(x.w - __bfloat162float(h3));
        ((__nv_bfloat162*)hi)[2 * i]     = __nv_bfloat162(h0, h1);
        ((__nv_bfloat162*)hi)[2 * i + 1] = __nv_bfloat162(h2, h3);
        ((__nv_bfloat162*)lo)[2 * i]     = __nv_bfloat162(l0, l1);
        ((__nv_bfloat162*)lo)[2 * i + 1] = __nv_bfloat162(l2, l3);
    }
}

// ---------------------------------------------------------------------------
// Tensor-core GEMM (NT): C[m,n] = sum_k A[m,k]*W[n,k] + bias[n], opt LeakyReLU
// A,W pre-split into bf16 hi/lo; acc = AhBh + AhBl + AlBh in fp32 (mma.sync).
// 128x128 CTA tile, 16 warps (4x4), 32x32 warp tile, K-chunks of 64 bf16.
// SW128-swizzled SMEM, 3-stage cp.async pipeline.
// ---------------------------------------------------------------------------
#define TILE_B      16384     // 128 rows x 128 bytes (64 bf16)
#define STAGE_BYTES 65536     // 4 tiles (Ah, Al, Bh, Bl)
#define NSTAGE      3

__global__ __launch_bounds__(512, 1)
void gemm_bf16x3(const __nv_bfloat16* __restrict__ Ah, const __nv_bfloat16* __restrict__ Al,
                 const __nv_bfloat16* __restrict__ Bh, const __nv_bfloat16* __restrict__ Bl,
                 const float* __restrict__ bias, float* __restrict__ Cout,
                 int M, int N, int K, int act)
{
    extern __shared__ char smem_raw[];
    char* sm = (char*)(((uintptr_t)smem_raw + 1023) & ~(uintptr_t)1023);
    const uint32_t smb = smem_u32(sm);

    const int tid  = threadIdx.x;
    const int wid  = tid >> 5;
    const int lane = tid & 31;
    const int m0   = blockIdx.y * 128;
    const int n0   = blockIdx.x * 128;
    const int wm   = wid >> 2;       // 0..3
    const int wn   = wid & 3;        // 0..3

    float acc[2][4][4];
#pragma unroll
    for (int i = 0; i < 2; i++)
#pragma unroll
        for (int j = 0; j < 4; j++)
#pragma unroll
            for (int r = 0; r < 4; r++) acc[i][j][r] = 0.f;

    const int nchunk = K >> 6;

    // ---- async tile loader for chunk c (stage = c % 3) ----
    auto issue_load = [&](int c) {
        const uint32_t sb = smb + (c % NSTAGE) * STAGE_BYTES;
        const int k0 = c << 6;
#pragma unroll
        for (int b = 0; b < 4; b++) {
            const __nv_bfloat16* src = (b == 0) ? Ah : (b == 1) ? Al
                                     : (b == 2) ? Bh : Bl;
            const int rb = (b < 2) ? m0 : n0;
            const uint32_t dstb = sb + b * TILE_B;
#pragma unroll
            for (int i = 0; i < 2; i++) {
                int idx = tid + i * 512;           // 0..1023 16B-slots
                int row = idx >> 3;
                int seg = idx & 7;
                const void* g = src + (size_t)(rb + row) * K + k0 + seg * 8;
                CP_ASYNC16(dstb + sw128(row * 128 + seg * 16), g);
            }
        }
        CP_COMMIT();
    };

    issue_load(0);
    if (nchunk > 1) issue_load(1);

    const int lrow = lane & 15;
    const int lseg = lane >> 4;

    for (int c = 0; c < nchunk; c++) {
        if (c + 1 < nchunk) { CP_WAIT1(); } else { CP_WAIT0(); }
        __syncthreads();
        if (c + 2 < nchunk) issue_load(c + 2);

        const uint32_t sb = smb + (c % NSTAGE) * STAGE_BYTES;
#pragma unroll
        for (int ks = 0; ks < 4; ks++) {
            const int kb = ks * 32 + lseg * 16;

            uint32_t a[2][4], bH[2][4], bL[2][4];
#pragma unroll
            for (int fm = 0; fm < 2; fm++)
                ldsm4(a[fm], sb + sw128((wm * 32 + fm * 16 + lrow) * 128 + kb));
#pragma unroll
            for (int g = 0; g < 2; g++)
                ldsm4(bH[g], sb + 2 * TILE_B +
                             sw128((wn * 32 + g * 16 + lrow) * 128 + kb));
#pragma unroll
            for (int g = 0; g < 2; g++)
                ldsm4(bL[g], sb + 3 * TILE_B +
                             sw128((wn * 32 + g * 16 + lrow) * 128 + kb));

            // Ah*Bh + Ah*Bl
#pragma unroll
            for (int fm = 0; fm < 2; fm++)
#pragma unroll
                for (int nf = 0; nf < 4; nf++) {
                    mma16816(acc[fm][nf], a[fm],
                             bH[nf >> 1][nf & 1], bH[nf >> 1][(nf & 1) + 2]);
                    mma16816(acc[fm][nf], a[fm],
                             bL[nf >> 1][nf & 1], bL[nf >> 1][(nf & 1) + 2]);
                }

            // Al*Bh (reuse bH, overwrite a with Al fragments)
#pragma unroll
            for (int fm = 0; fm < 2; fm++)
                ldsm4(a[fm], sb + TILE_B +
                             sw128((wm * 32 + fm * 16 + lrow) * 128 + kb));
#pragma unroll
            for (int fm = 0; fm < 2; fm++)
#pragma unroll
                for (int nf = 0; nf < 4; nf++)
                    mma16816(acc[fm][nf], a[fm],
                             bH[nf >> 1][nf & 1], bH[nf >> 1][(nf & 1) + 2]);
        }
    }

    // ---- epilogue: direct fragment stores with bias (+LeakyReLU) ----
#pragma unroll
    for (int fm = 0; fm < 2; fm++) {
        const int r0 = m0 + wm * 32 + fm * 16 + (lane >> 2);
#pragma unroll
        for (int nf = 0; nf < 4; nf++) {
            const int col = n0 + wn * 32 + nf * 8 + (lane & 3) * 2;
            float2 bv = *(const float2*)(bias + col);
            float2 v0, v1;
            v0.x = acc[fm][nf][0] + bv.x;
            v0.y = acc[fm][nf][1] + bv.y;
            v1.x = acc[fm][nf][2] + bv.x;
            v1.y = acc[fm][nf][3] + bv.y;
            if (act) {
                v0.x = v0.x >= 0.f ? v0.x : 0.01f * v0.x;
                v0.y = v0.y >= 0.f ? v0.y : 0.01f * v0.y;
                v1.x = v1.x >= 0.f ? v1.x : 0.01f * v1.x;
                v1.y = v1.y >= 0.f ? v1.y : 0.01f * v1.y;
            }
            *(float2*)(Cout + (size_t)r0 * N + col)       = v0;
            *(float2*)(Cout + (size_t)(r0 + 8) * N + col) = v1;
        }
    }
}

// ---------------------------------------------------------------------------
// Tiny 6x6 attention: one warp per (token n, head h).
// Emits context directly as split hi/lo bf16 for the O-projection GEMM.
// ---------------------------------------------------------------------------
__device__ __forceinline__ float warpAllSum(float v)
{
#pragma unroll
    for (int o = 16; o; o >>= 1) v += __shfl_xor_sync(0xffffffffu, v, o);
    return v;
}

__global__ __launch_bounds__(256)
void attn6_kernel(const float* __restrict__ Q, const float* __restrict__ K,
                  const float* __restrict__ V,
                  __nv_bfloat16* __restrict__ CH, __nv_bfloat16* __restrict__ CL)
{
    const int warp = threadIdx.x >> 5;
    const int lane = threadIdx.x & 31;
    const int idx  = blockIdx.x * 8 + warp;
    const int n = idx >> 4;
    const int h = idx & 15;

    const size_t base = (size_t)n * E_DIM + h * D_HEAD + 2 * lane;

    float2 q[6], k[6], v[6];
#pragma unroll
    for (int j = 0; j < 6; j++) {
        size_t off = base + (size_t)j * NTOK * E_DIM;
        q[j] = *(const float2*)(Q + off);
        k[j] = *(const float2*)(K + off);
        v[j] = *(const float2*)(V + off);
    }

    float s[6][6];
#pragma unroll
    for (int i = 0; i < 6; i++)
#pragma unroll
        for (int j = 0; j < 6; j++) {
            float p = q[i].x * k[j].x + q[i].y * k[j].y;
            s[i][j] = warpAllSum(p) * 0.125f;
        }

#pragma unroll
    for (int i = 0; i < 6; i++) {
        float mx = s[i][0];
#pragma unroll
        for (int j = 1; j < 6; j++) mx = fmaxf(mx, s[i][j]);
        float se = 0.f;
#pragma unroll
        for (int j = 0; j < 6; j++) { s[i][j] = __expf(s[i][j] - mx); se += s[i][j]; }
        float inv = 1.f / se;
#pragma unroll
        for (int j = 0; j < 6; j++) s[i][j] *= inv;
    }

#pragma unroll
    for (int i = 0; i < 6; i++) {
        float2 acc = make_float2(0.f, 0.f);
#pragma unroll
        for (int j = 0; j < 6; j++) {
            acc.x += s[i][j] * v[j].x;
            acc.y += s[i][j] * v[j].y;
        }
        __nv_bfloat16 h0 = __float2bfloat16(acc.x);
        __nv_bfloat16 h1 = __float2bfloat16(acc.y);
        __nv_bfloat16 l0 = __float2bfloat16(acc.x - __bfloat162float(h0));
        __nv_bfloat16 l1 = __float2bfloat16(acc.y - __bfloat162float(h1));
        size_t off = base + (size_t)i * NTOK * E_DIM;
        *(__nv_bfloat162*)(CH + off) = __nv_bfloat162(h0, h1);
        *(__nv_bfloat162*)(CL + off) = __nv_bfloat162(l0, l1);
    }
}

// ---------------------------------------------------------------------------
// Block-wide allreduce of (sum, sumsq)
// ---------------------------------------------------------------------------
__device__ __forceinline__ float2 blockAllReduce2(float2 v)
{
    __shared__ float2 sh[8];
    const int lane = threadIdx.x & 31;
    const int wid  = threadIdx.x >> 5;
#pragma unroll
    for (int o = 16; o; o >>= 1) {
        v.x += __shfl_xor_sync(0xffffffffu, v.x, o);
        v.y += __shfl_xor_sync(0xffffffffu, v.y, o);
    }
    if (lane == 0) sh[wid] = v;
    __syncthreads();
    if (wid == 0) {
        float2 t = (lane < 8) ? sh[lane] : make_float2(0.f, 0.f);
#pragma unroll
        for (int o = 4; o; o >>= 1) {
            t.x += __shfl_xor_sync(0xffffffffu, t.x, o);
            t.y += __shfl_xor_sync(0xffffffffu, t.y, o);
        }
        if (lane == 0) sh[0] = t;
    }
    __syncthreads();
    float2 r = sh[0];
    __syncthreads();
    return r;
}

// ---------------------------------------------------------------------------
// LN1(out + st) per (j, n) row, then weighted fusion over j.
// Emits the fused row directly as split hi/lo bf16 for the final GEMM.
// ---------------------------------------------------------------------------
__global__ __launch_bounds__(256)
void ln1_fuse_kernel(const float* __restrict__ OP, const float* __restrict__ ST,
                     const float* __restrict__ g, const float* __restrict__ b,
                     const float* __restrict__ fw,
                     __nv_bfloat16* __restrict__ FH, __nv_bfloat16* __restrict__ FL)
{
    const int n   = blockIdx.x;
    const int tid = threadIdx.x;

    float w[6];
    {
        float f[6], mx = -1e30f;
#pragma unroll
        for (int j = 0; j < 6; j++) { f[j] = fw[j]; mx = fmaxf(mx, f[j]); }
        float se = 0.f;
#pragma unroll
        for (int j = 0; j < 6; j++) { w[j] = expf(f[j] - mx); se += w[j]; }
        float inv = 1.f / se;
#pragma unroll
        for (int j = 0; j < 6; j++) w[j] *= inv;
    }

    float4 gg = ((const float4*)g)[tid];
    float4 bb = ((const float4*)b)[tid];
    float4 acc = make_float4(0.f, 0.f, 0.f, 0.f);

    for (int j = 0; j < 6; j++) {
        size_t roff = ((size_t)j * NTOK + n) * E_DIM;
        float4 x = ((const float4*)(OP + roff))[tid];
        float4 y = ((const float4*)(ST + roff))[tid];
        x.x += y.x; x.y += y.y; x.z += y.z; x.w += y.w;

        float2 r = make_float2(x.x + x.y + x.z + x.w,
                               x.x * x.x + x.y * x.y + x.z * x.z + x.w * x.w);
        r = blockAllReduce2(r);
        float mean = r.x * (1.f / 1024.f);
        float var  = r.y * (1.f / 1024.f) - mean * mean;
        float rstd = rsqrtf(var + 1e-5f);

        acc.x += w[j] * ((x.x - mean) * rstd * gg.x + bb.x);
        acc.y += w[j] * ((x.y - mean) * rstd * gg.y + bb.y);
        acc.z += w[j] * ((x.z - mean) * rstd * gg.z + bb.z);
        acc.w += w[j] * ((x.w - mean) * rstd * gg.w + bb.w);
    }

    __nv_bfloat16 h0 = __float2bfloat16(acc.x);
    __nv_bfloat16 h1 = __float2bfloat16(acc.y);
    __nv_bfloat16 h2 = __float2bfloat16(acc.z);
    __nv_bfloat16 h3 = __float2bfloat16(acc.w);
    __nv_bfloat16 l0 = __float2bfloat16(acc.x - __bfloat162float(h0));
    __nv_bfloat16 l1 = __float2bfloat16(acc.y - __bfloat162float(h1));
    __nv_bfloat16 l2 = __float2bfloat16(acc.z - __bfloat162float(h2));
    __nv_bfloat16 l3 = __float2bfloat16(acc.w - __bfloat162float(h3));
    size_t o2 = (size_t)n * 512 + 2 * tid;
    ((__nv_bfloat162*)FH)[o2]     = __nv_bfloat162(h0, h1);
    ((__nv_bfloat162*)FH)[o2 + 1] = __nv_bfloat162(h2, h3);
    ((__nv_bfloat162*)FL)[o2]     = __nv_bfloat162(l0, l1);
    ((__nv_bfloat162*)FL)[o2 + 1] = __nv_bfloat162(l2, l3);
}

// ---------------------------------------------------------------------------
// LN2 per token row
// ---------------------------------------------------------------------------
__global__ __launch_bounds__(256)
void ln2_kernel(const float* __restrict__ Hbuf, const float* __restrict__ g,
                const float* __restrict__ b, float* __restrict__ out)
{
    const int n   = blockIdx.x;
    const int tid = threadIdx.x;

    float4 x = ((const float4*)(Hbuf + (size_t)n * HID))[tid];
    float2 r = make_float2(x.x + x.y + x.z + x.w,
                           x.x * x.x + x.y * x.y + x.z * x.z + x.w * x.w);
    r = blockAllReduce2(r);
    float mean = r.x * (1.f / 1024.f);
    float var  = r.y * (1.f / 1024.f) - mean * mean;
    float rstd = rsqrtf(var + 1e-5f);

    float4 gg = ((const float4*)g)[tid];
    float4 bb = ((const float4*)b)[tid];
    float4 o;
    o.x = (x.x - mean) * rstd * gg.x + bb.x;
    o.y = (x.y - mean) * rstd * gg.y + bb.y;
    o.z = (x.z - mean) * rstd * gg.z + bb.z;
    o.w = (x.w - mean) * rstd * gg.w + bb.w;
    ((float4*)(out + (size_t)n * HID))[tid] = o;
}

// ---------------------------------------------------------------------------
// Launch
// ---------------------------------------------------------------------------
extern "C" void kernel_launch(void* const* d_in, const int* in_sizes, int n_in,
                              void* d_out, int out_size)
{
    const float* st    = (const float*)d_in[0];
    const float* Wq    = (const float*)d_in[1];
    const float* bq    = (const float*)d_in[2];
    const float* Wk    = (const float*)d_in[3];
    const float* bk    = (const float*)d_in[4];
    const float* Wv    = (const float*)d_in[5];
    const float* bv    = (const float*)d_in[6];
    const float* Wo    = (const float*)d_in[7];
    const float* bo    = (const float*)d_in[8];
    const float* ln1_g = (const float*)d_in[9];
    const float* ln1_b = (const float*)d_in[10];
    const float* fw    = (const float*)d_in[11];
    const float* Wf    = (const float*)d_in[12];
    const float* bf    = (const float*)d_in[13];
    const float* ln2_g = (const float*)d_in[14];
    const float* ln2_b = (const float*)d_in[15];
    float* out = (float*)d_out;

    void* sp = nullptr;
    cudaGetSymbolAddress(&sp, g_scratch);
    float* S = (float*)sp;
    void* bp = nullptr;
    cudaGetSymbolAddress(&bp, g_bf);
    __nv_bfloat16* BF = (__nv_bfloat16*)bp;

    const int GSM = NSTAGE * STAGE_BYTES + 1024;   // 197632
    cudaFuncSetAttribute(gemm_bf16x3,
                         cudaFuncAttributeMaxDynamicSharedMemorySize, GSM);

    dim3 blk(256);
    dim3 gblk(512);
    dim3 gBig(E_DIM / 128, NROWS / 128);   // (8, 384)
    dim3 gF(HID / 128, NTOK / 128);        // (8, 64)

    __nv_bfloat16* stH = BF + BOFF_STH;
    __nv_bfloat16* stL = BF + BOFF_STL;
    __nv_bfloat16* cxH = BF + BOFF_CXH;
    __nv_bfloat16* cxL = BF + BOFF_CXL;
    __nv_bfloat16* fH  = BF + BOFF_FH;
    __nv_bfloat16* fL  = BF + BOFF_FL;
    __nv_bfloat16* wB  = BF + BOFF_W;      // 10 x 1048576

    // split-convert the shared activation input and the five weight matrices
    cvt_split<<<2048, blk>>>(st, stH, stL, NROWS * E_DIM / 4);
    cvt_split<<<256, blk>>>(Wq, wB + 0 * 1048576, wB + 1 * 1048576, 262144);
    cvt_split<<<256, blk>>>(Wk, wB + 2 * 1048576, wB + 3 * 1048576, 262144);
    cvt_split<<<256, blk>>>(Wv, wB + 4 * 1048576, wB + 5 * 1048576, 262144);
    cvt_split<<<256, blk>>>(Wo, wB + 6 * 1048576, wB + 7 * 1048576, 262144);
    cvt_split<<<256, blk>>>(Wf, wB + 8 * 1048576, wB + 9 * 1048576, 262144);

    // Q/K/V projections (tensor cores, bf16x3)
    gemm_bf16x3<<<gBig, gblk, GSM>>>(stH, stL, wB + 0 * 1048576, wB + 1 * 1048576,
                                     bq, S + OFF_Q, NROWS, E_DIM, E_DIM, 0);
    gemm_bf16x3<<<gBig, gblk, GSM>>>(stH, stL, wB + 2 * 1048576, wB + 3 * 1048576,
                                     bk, S + OFF_K, NROWS, E_DIM, E_DIM, 0);
    gemm_bf16x3<<<gBig, gblk, GSM>>>(stH, stL, wB + 4 * 1048576, wB + 5 * 1048576,
                                     bv, S + OFF_V, NROWS, E_DIM, E_DIM, 0);

    // tiny attention -> split bf16 context
    attn6_kernel<<<(NTOK * H_HEADS) / 8, blk>>>(S + OFF_Q, S + OFF_K, S + OFF_V,
                                                cxH, cxL);

    // output projection
    gemm_bf16x3<<<gBig, gblk, GSM>>>(cxH, cxL, wB + 6 * 1048576, wB + 7 * 1048576,
                                     bo, S + OFF_O, NROWS, E_DIM, E_DIM, 0);

    // LN1 + fusion -> split bf16 fused rows
    ln1_fuse_kernel<<<NTOK, blk>>>(S + OFF_O, st, ln1_g, ln1_b, fw, fH, fL);

    // final projection + LeakyReLU
    gemm_bf16x3<<<gF, gblk, GSM>>>(fH, fL, wB + 8 * 1048576, wB + 9 * 1048576,
                                   bf, S + OFF_H, NTOK, HID, E_DIM, 1);

    // LN2
    ln2_kernel<<<NTOK, blk>>>(S + OFF_H, ln2_g, ln2_b, out);
}